// round 1
// baseline (speedup 1.0000x reference)
#include <cuda_runtime.h>
#include <math.h>

// Problem constants
#define HW     36864          // 192*192
#define CIN    64
#define BS     2
#define NQ     4096           // 64*64 output grid
#define COUT   69             // rm_cos, var, qn(3), mapped(64)

// Tiling
#define QT     128            // queries per block
#define MT     48             // m per chunk
#define NSEG   32             // m segments (split-K)
#define SEGLEN (HW / NSEG)    // 1152
#define NCHUNK (SEGLEN / MT)  // 24
#define CPAD   68             // padded channel row for vals tile
#define MAXV   1024           // upper bound on valid query count (~804)

struct QParam {
    int nv;
    int rowstart[65];   // cumulative valid count before row v
    int umin[64];       // first valid u in row v
};

// Split-K partials (static device scratch; no allocation in kernel_launch)
__device__ __align__(16) float g_max [BS][NSEG][MAXV];
__device__ __align__(16) float g_sumw[BS][NSEG][MAXV];
__device__ __align__(16) float g_swc [BS][NSEG][MAXV];
__device__ __align__(16) float g_sq  [BS][NSEG][MAXV][4];
__device__ __align__(16) float g_acc [BS][NSEG][MAXV][CIN];

__device__ __forceinline__ int slot_to_qidx(const QParam& qp, int slot)
{
    if (slot >= qp.nv) return -1;
    int lo = 0, hi = 64;
    while (hi - lo > 1) {
        int mid = (lo + hi) >> 1;
        if (qp.rowstart[mid] <= slot) lo = mid; else hi = mid;
    }
    return lo * 64 + qp.umin[lo] + (slot - qp.rowstart[lo]);
}

__device__ __forceinline__ void qn_of(int qidx, float& x, float& y, float& z)
{
    if (qidx < 0) { x = y = z = 0.f; return; }
    int v = qidx >> 6, u = qidx & 63;
    float p =  4.0f * ((u + 0.5f) * (1.0f / 64.0f) - 0.5f);
    float q = -4.0f * ((v + 0.5f) * (1.0f / 64.0f) - 0.5f);
    float r2 = p * p + q * q;           // exact in fp32 for this lattice
    if (r2 < 1.0f) {
        float inv = 1.0f / (1.0f + r2);
        x = 2.0f * p * inv;
        y = 2.0f * q * inv;
        z = (1.0f - r2) * inv;
    } else {
        x = y = z = 0.f;
    }
}

// -------------------------------------------------------------------------
// Main kernel: block = (qblock, seg, b).  Pass A: per-query segment max.
// Pass B: chunked shared-tile accumulation of sumw / sum w*cos / sum w*v^2 /
// sum w*vals[c] with segment-local max stabilization.
// -------------------------------------------------------------------------
__global__ __launch_bounds__(256, 2)
void k_main(const float* __restrict__ fea, const float* __restrict__ nrm,
            const float* __restrict__ msk, const float* __restrict__ lqn,
            QParam qp)
{
    __shared__ __align__(16) float vals_sh[MT][CPAD];
    __shared__ __align__(16) float w_sh[MT][QT];
    __shared__ float nsh[3][MT];
    __shared__ float msh[MT];
    __shared__ float maxsh[QT];

    const int qb  = blockIdx.x;
    const int seg = blockIdx.y;
    const int b   = blockIdx.z;
    const int t   = threadIdx.x;
    const int slot0 = qb * QT;
    const float scale = __expf(lqn[0]) * 0.5773502691896258f; // exp(lqn)/sqrt(3)

    const float* nb = nrm + (size_t)b * 3 * HW;
    const float* fb = fea + (size_t)b * CIN * HW;
    const float* mb = msk + (size_t)b * HW;
    const int m0 = seg * SEGLEN;

    // ---- pass A: per-query max of cos over this m segment ----
    {
        const int ml = t & 31, qg = t >> 5;   // 8 groups of 16 queries
        float qx[16], qy[16], qz[16], mx[16];
        #pragma unroll
        for (int j = 0; j < 16; j++) {
            int qi = slot_to_qidx(qp, slot0 + qg * 16 + j);
            qn_of(qi, qx[j], qy[j], qz[j]);
            mx[j] = -1e30f;
        }
        for (int i = ml; i < SEGLEN; i += 32) {
            float nx = nb[m0 + i];
            float ny = nb[HW + m0 + i];
            float nz = nb[2 * HW + m0 + i];
            #pragma unroll
            for (int j = 0; j < 16; j++) {
                float c = qx[j] * nx + qy[j] * ny + qz[j] * nz;
                mx[j] = fmaxf(mx[j], c);
            }
        }
        #pragma unroll
        for (int off = 16; off > 0; off >>= 1) {
            #pragma unroll
            for (int j = 0; j < 16; j++)
                mx[j] = fmaxf(mx[j], __shfl_xor_sync(0xffffffffu, mx[j], off));
        }
        if (ml == 0) {
            #pragma unroll
            for (int j = 0; j < 16; j++) {
                maxsh[qg * 16 + j] = mx[j];
                g_max[b][seg][slot0 + qg * 16 + j] = mx[j];
            }
        }
    }
    __syncthreads();

    // ---- roles for pass B ----
    // stage1 (w computation): thread -> (query s_q, half s_h of the m chunk)
    const int s_q = t >> 1, s_h = t & 1;
    float s_qx, s_qy, s_qz;
    qn_of(slot_to_qidx(qp, slot0 + s_q), s_qx, s_qy, s_qz);
    const float s_max = maxsh[s_q];
    float a_sumw = 0.f, a_swc = 0.f, a_s0 = 0.f, a_s1 = 0.f, a_s2 = 0.f;

    // stage2 (GEMM): thread -> 4 queries x 8 channels register tile
    const int tx = t & 7, ty = t >> 3;
    float acc[4][8];
    #pragma unroll
    for (int i = 0; i < 4; i++) {
        #pragma unroll
        for (int j = 0; j < 8; j++) acc[i][j] = 0.f;
    }

    for (int ch = 0; ch < NCHUNK; ch++) {
        const int mb0 = m0 + ch * MT;

        // load tiles: vals (64 x 48, transposed into [m][c]), normals, mask
        for (int i = t; i < CIN * (MT / 4); i += 256) {
            int c  = i / (MT / 4);
            int mi = (i - c * (MT / 4)) * 4;
            float4 v = *(const float4*)(fb + (size_t)c * HW + mb0 + mi);
            vals_sh[mi    ][c] = v.x;
            vals_sh[mi + 1][c] = v.y;
            vals_sh[mi + 2][c] = v.z;
            vals_sh[mi + 3][c] = v.w;
        }
        if (t < 3 * MT) {
            int d = t / MT, mi = t - d * MT;
            nsh[d][mi] = nb[(size_t)d * HW + mb0 + mi];
        } else if (t < 4 * MT) {
            int mi = t - 3 * MT;
            msh[mi] = mb[mb0 + mi];
        }
        __syncthreads();

        // stage1: w tile + extras
        #pragma unroll 4
        for (int k = 0; k < MT / 2; k++) {
            int mi = s_h * (MT / 2) + k;
            float c = s_qx * nsh[0][mi] + s_qy * nsh[1][mi] + s_qz * nsh[2][mi];
            float w = __expf(scale * (c - s_max)) * msh[mi];
            w_sh[mi][s_q] = w;
            a_sumw += w;
            a_swc  += w * c;
            float v0 = vals_sh[mi][61], v1 = vals_sh[mi][62], v2 = vals_sh[mi][63];
            a_s0 += w * v0 * v0;
            a_s1 += w * v1 * v1;
            a_s2 += w * v2 * v2;
        }
        __syncthreads();

        // stage2: 128q x 64c x 48m accumulation
        #pragma unroll 8
        for (int mi = 0; mi < MT; mi++) {
            const float4 wv = *(const float4*)(&w_sh[mi][ty * 4]);
            const float4 va = *(const float4*)(&vals_sh[mi][tx * 8]);
            const float4 vb = *(const float4*)(&vals_sh[mi][tx * 8 + 4]);
            const float wr[4] = {wv.x, wv.y, wv.z, wv.w};
            const float vr[8] = {va.x, va.y, va.z, va.w, vb.x, vb.y, vb.z, vb.w};
            #pragma unroll
            for (int i = 0; i < 4; i++) {
                #pragma unroll
                for (int j = 0; j < 8; j++)
                    acc[i][j] = fmaf(wr[i], vr[j], acc[i][j]);
            }
        }
        __syncthreads();
    }

    // ---- write partials ----
    {
        float o_sumw = a_sumw + __shfl_xor_sync(0xffffffffu, a_sumw, 1);
        float o_swc  = a_swc  + __shfl_xor_sync(0xffffffffu, a_swc, 1);
        float o_s0   = a_s0   + __shfl_xor_sync(0xffffffffu, a_s0, 1);
        float o_s1   = a_s1   + __shfl_xor_sync(0xffffffffu, a_s1, 1);
        float o_s2   = a_s2   + __shfl_xor_sync(0xffffffffu, a_s2, 1);
        if (s_h == 0) {
            int slot = slot0 + s_q;
            g_sumw[b][seg][slot]  = o_sumw;
            g_swc [b][seg][slot]  = o_swc;
            g_sq  [b][seg][slot][0] = o_s0;
            g_sq  [b][seg][slot][1] = o_s1;
            g_sq  [b][seg][slot][2] = o_s2;
        }
    }
    #pragma unroll
    for (int i = 0; i < 4; i++) {
        int slot = slot0 + ty * 4 + i;
        float4 o0 = make_float4(acc[i][0], acc[i][1], acc[i][2], acc[i][3]);
        float4 o1 = make_float4(acc[i][4], acc[i][5], acc[i][6], acc[i][7]);
        *(float4*)(&g_acc[b][seg][slot][tx * 8])     = o0;
        *(float4*)(&g_acc[b][seg][slot][tx * 8 + 4]) = o1;
    }
}

// -------------------------------------------------------------------------
// Finalize: merge segments with online-softmax rescale, normalize, write out.
// One block (64 threads) per (valid slot, batch).
// -------------------------------------------------------------------------
__global__ void k_final(float* __restrict__ out, const float* __restrict__ lqn,
                        QParam qp)
{
    const int slot = blockIdx.x;
    const int b    = blockIdx.y;
    const int t    = threadIdx.x;
    if (slot >= qp.nv) return;
    const int qidx = slot_to_qidx(qp, slot);
    const float scale = __expf(lqn[0]) * 0.5773502691896258f;

    __shared__ float sc[NSEG];
    __shared__ float sD, s_swc, s_sq[3], s_mean[3];

    if (t == 0) {
        float mg = -1e30f;
        for (int i = 0; i < NSEG; i++) mg = fmaxf(mg, g_max[b][i][slot]);
        float sumw = 0.f, swc = 0.f, q0 = 0.f, q1 = 0.f, q2 = 0.f;
        for (int i = 0; i < NSEG; i++) {
            float s = __expf(scale * (g_max[b][i][slot] - mg));
            sc[i] = s;
            sumw += s * g_sumw[b][i][slot];
            swc  += s * g_swc [b][i][slot];
            q0   += s * g_sq  [b][i][slot][0];
            q1   += s * g_sq  [b][i][slot][1];
            q2   += s * g_sq  [b][i][slot][2];
        }
        sD = sumw + 1e-9f;
        s_swc = swc; s_sq[0] = q0; s_sq[1] = q1; s_sq[2] = q2;
    }
    __syncthreads();

    const float D = sD;
    float a = 0.f;
    for (int i = 0; i < NSEG; i++) a += sc[i] * g_acc[b][i][slot][t];
    float mapped = a / D;
    out[((size_t)b * COUT + 5 + t) * NQ + qidx] = mapped;
    if (t >= 61) s_mean[t - 61] = mapped;
    __syncthreads();

    if (t == 0) {
        float var = (s_sq[0] / D - s_mean[0] * s_mean[0])
                  + (s_sq[1] / D - s_mean[1] * s_mean[1])
                  + (s_sq[2] / D - s_mean[2] * s_mean[2]);
        float x, y, z;
        qn_of(qidx, x, y, z);
        out[((size_t)b * COUT + 0) * NQ + qidx] = s_swc / D;
        out[((size_t)b * COUT + 1) * NQ + qidx] = var;
        out[((size_t)b * COUT + 2) * NQ + qidx] = x;
        out[((size_t)b * COUT + 3) * NQ + qidx] = y;
        out[((size_t)b * COUT + 4) * NQ + qidx] = z;
    }
}

__global__ void k_zero(float* __restrict__ out, int n)
{
    int i = blockIdx.x * 256 + threadIdx.x;
    if (i < n) out[i] = 0.f;
}

extern "C" void kernel_launch(void* const* d_in, const int* in_sizes, int n_in,
                              void* d_out, int out_size)
{
    const float* fea = (const float*)d_in[0];
    const float* nrm = (const float*)d_in[1];
    const float* msk = (const float*)d_in[2];
    const float* lqn = (const float*)d_in[3];
    float* out = (float*)d_out;

    // Host-side analytic valid-query table (deterministic, capture-safe).
    QParam qp;
    int n = 0;
    for (int v = 0; v < 64; v++) {
        qp.rowstart[v] = n;
        int first = -1;
        for (int u = 0; u < 64; u++) {
            double p =  4.0 * ((u + 0.5) / 64.0 - 0.5);
            double q = -4.0 * ((v + 0.5) / 64.0 - 0.5);
            if (p * p + q * q < 1.0) {
                if (first < 0) first = u;
                n++;
            }
        }
        qp.umin[v] = (first < 0) ? 0 : first;
    }
    qp.rowstart[64] = n;
    qp.nv = n;

    int qblocks = (n + QT - 1) / QT;

    k_zero<<<(out_size + 255) / 256, 256>>>(out, out_size);
    dim3 g2(qblocks, NSEG, BS);
    k_main<<<g2, 256>>>(fea, nrm, msk, lqn, qp);
    k_final<<<dim3(n, BS), 64>>>(out, lqn, qp);
}

// round 3
// speedup vs baseline: 3.5861x; 3.5861x over previous
#include <cuda_runtime.h>
#include <cuda_fp16.h>
#include <math.h>
#include <stdint.h>

// Problem constants
#define HW     36864          // 192*192
#define CIN    64
#define BS     2
#define NQ     4096
#define COUT   69

// Tiling
#define QT     128            // queries per block
#define CK     64             // m per chunk
#define NSEG   21             // m partitions -> grid 7*21*2 = 294 ~= 148 SM * occ2
#define TCH    (HW / CK)      // 576 total chunks
#define MAXV   896            // 7 * 128 slots
#define PSTR   144            // P/V shared row stride in bytes (72 fp16)

struct QParam {
    int nv;
    int rowstart[65];
    int umin[64];
};

// Split-K partials
__device__ __align__(16) float g_sumw[BS][NSEG][MAXV];
__device__ __align__(16) float g_swc [BS][NSEG][MAXV];
__device__ __align__(16) float g_sq  [BS][NSEG][MAXV][4];
__device__ __align__(16) float g_acc [BS][NSEG][MAXV][CIN];

// ---------------- PTX helpers ----------------
__device__ __forceinline__ uint32_t smem_u32(const void* p) {
    uint32_t a;
    asm("{ .reg .u64 t; cvta.to.shared.u64 t, %1; cvt.u32.u64 %0, t; }"
        : "=r"(a) : "l"(p));
    return a;
}

#define FMA2(d, a, b, c) asm("fma.rn.f32x2 %0, %1, %2, %3;" : "=l"(d) : "l"(a), "l"(b), "l"(c))
#define MUL2(d, a, b)    asm("mul.rn.f32x2 %0, %1, %2;"     : "=l"(d) : "l"(a), "l"(b))
#define ADD2(d, a, b)    asm("add.rn.f32x2 %0, %1, %2;"     : "=l"(d) : "l"(a), "l"(b))

__device__ __forceinline__ unsigned long long pk2(float lo, float hi) {
    unsigned long long r;
    asm("mov.b64 %0, {%1, %2};" : "=l"(r) : "f"(lo), "f"(hi));
    return r;
}
__device__ __forceinline__ void upk2(unsigned long long v, float& lo, float& hi) {
    asm("mov.b64 {%0, %1}, %2;" : "=f"(lo), "=f"(hi) : "l"(v));
}
__device__ __forceinline__ float ex2f(float x) {
    float r; asm("ex2.approx.ftz.f32 %0, %1;" : "=f"(r) : "f"(x)); return r;
}
__device__ __forceinline__ uint32_t cvt_f16x2(float lo, float hi) {
    uint32_t r; asm("cvt.rn.f16x2.f32 %0, %1, %2;" : "=r"(r) : "f"(hi), "f"(lo)); return r;
}
__device__ __forceinline__ void ldsm_x4(uint32_t& r0, uint32_t& r1, uint32_t& r2,
                                        uint32_t& r3, uint32_t addr) {
    asm volatile("ldmatrix.sync.aligned.m8n8.x4.shared.b16 {%0,%1,%2,%3}, [%4];"
                 : "=r"(r0), "=r"(r1), "=r"(r2), "=r"(r3) : "r"(addr));
}
__device__ __forceinline__ void mma16816(float* d, const uint32_t* a,
                                         uint32_t b0, uint32_t b1) {
    asm volatile("mma.sync.aligned.m16n8k16.row.col.f32.f16.f16.f32 "
                 "{%0,%1,%2,%3}, {%4,%5,%6,%7}, {%8,%9}, {%0,%1,%2,%3};"
                 : "+f"(d[0]), "+f"(d[1]), "+f"(d[2]), "+f"(d[3])
                 : "r"(a[0]), "r"(a[1]), "r"(a[2]), "r"(a[3]), "r"(b0), "r"(b1));
}

// ---------------- query helpers ----------------
__device__ __forceinline__ bool q_valid(int u, int v) {
    int du = 2 * u - 63, dv = 2 * v - 63;
    return du * du + dv * dv < 1024;   // exact: matches host double test
}

__device__ __forceinline__ int slot_to_qidx(const QParam& qp, int slot) {
    if (slot >= qp.nv) return -1;
    int lo = 0, hi = 64;
    while (hi - lo > 1) {
        int mid = (lo + hi) >> 1;
        if (qp.rowstart[mid] <= slot) lo = mid; else hi = mid;
    }
    return lo * 64 + qp.umin[lo] + (slot - qp.rowstart[lo]);
}

__device__ __forceinline__ void qn_of(int qidx, float& x, float& y, float& z) {
    if (qidx < 0) { x = y = z = 0.f; return; }
    int v = qidx >> 6, u = qidx & 63;
    if (!q_valid(u, v)) { x = y = z = 0.f; return; }
    float p =  4.0f * ((u + 0.5f) * (1.0f / 64.0f) - 0.5f);
    float q = -4.0f * ((v + 0.5f) * (1.0f / 64.0f) - 0.5f);
    float r2 = p * p + q * q;       // exact in fp32 for this lattice
    float inv = 1.0f / (1.0f + r2);
    x = 2.0f * p * inv;
    y = 2.0f * q * inv;
    z = (1.0f - r2) * inv;
}

// -------------------------------------------------------------------------
// Main kernel: grid (7, NSEG, BS), 256 threads, occ 2.
// Per 64-m chunk: load V tile fp32->fp16 + packed normals/mask/sq;
// w = exp(scale*(cos-off))*mask in packed f32x2 -> fp16 P tile;
// mma.sync m16n8k16 accumulates P(128x64m) * V^T(64m x 64ch) in registers.
// -------------------------------------------------------------------------
__global__ __launch_bounds__(256, 2)
void k_main(const float* __restrict__ fea, const float* __restrict__ nrm,
            const float* __restrict__ msk, const float* __restrict__ lqn,
            QParam qp)
{
    __shared__ __align__(16) float4 pA[32];          // {nx0,nx1,ny0,ny1} per m-pair
    __shared__ __align__(16) float4 pB[32];          // {nz0,nz1,mk0,mk1}
    __shared__ __align__(16) float4 pC[32];          // {s61_0,s61_1,s62_0,s62_1}
    __shared__ __align__(16) float2 pD[32];          // {s63_0,s63_1}
    __shared__ __align__(16) char   P_sh[QT * PSTR]; // 128 x 72 fp16
    __shared__ __align__(16) char   V_sh[CIN * PSTR];// 64 x 72 fp16

    const int t = threadIdx.x;
    const int wid = t >> 5, lid = t & 31;
    const int qb = blockIdx.x, seg = blockIdx.y, b = blockIdx.z;
    const int slot0 = qb * QT;

    const uint32_t sbP = smem_u32(P_sh);
    const uint32_t sbV = smem_u32(V_sh);

    const float scale = __expf(lqn[0]) * 0.57735026918962576f;  // exp(lqn)/sqrt(3)
    const float off   = 1.0f - 8.0f / scale;                    // fp16-safe offset
    const float k2c   = scale * 1.44269504088896341f;           // nats -> log2
    const unsigned long long kk2 = pk2(k2c, k2c);
    const unsigned long long bb2 = pk2(-k2c * off, -k2c * off);

    const float* nb = nrm + (size_t)b * 3 * HW;
    const float* fb = fea + (size_t)b * CIN * HW;
    const float* mb = msk + (size_t)b * HW;

    // w-gen role
    const int q = t >> 1, mh = t & 1;
    float qx, qy, qz;
    qn_of(slot_to_qidx(qp, slot0 + q), qx, qy, qz);
    const unsigned long long qxx = pk2(qx, qx), qyy = pk2(qy, qy), qzz = pk2(qz, qz);

    // V-load role
    const int vc = t >> 2, vmq = (t & 3) * 16;

    // mma role: warp tile 32q x 32ch
    const int wq = (wid & 3) * 32;
    const int wc = (wid >> 2) * 32;
    const uint32_t aAddr = sbP + (uint32_t)((wq + (lid & 15)) * PSTR + (lid >> 4) * 16);
    const uint32_t bAddr = sbV + (uint32_t)((wc + (lid & 15)) * PSTR + (lid >> 4) * 16);

    float acc[2][4][4];
    #pragma unroll
    for (int i = 0; i < 2; i++)
        #pragma unroll
        for (int j = 0; j < 4; j++)
            #pragma unroll
            for (int k = 0; k < 4; k++) acc[i][j][k] = 0.f;

    unsigned long long a_sumw = 0ull, a_swc = 0ull, a_s0 = 0ull, a_s1 = 0ull, a_s2 = 0ull;

    const int c0 = (seg * TCH) / NSEG;
    const int c1 = ((seg + 1) * TCH) / NSEG;

    for (int ci = c0; ci < c1; ci++) {
        const int mb0 = ci * CK;
        __syncthreads();   // protect P/V/pA.. against previous chunk's readers

        // ---- load: V tile (fp32->fp16), squares, normals, mask ----
        {
            const float* src = fb + (size_t)vc * HW + mb0 + vmq;
            char* vrow = V_sh + vc * PSTR + vmq * 2;
            #pragma unroll
            for (int k = 0; k < 4; k++) {
                const float4 v = *(const float4*)(src + k * 4);
                *(uint2*)(vrow + k * 8) =
                    make_uint2(cvt_f16x2(v.x, v.y), cvt_f16x2(v.z, v.w));
                if (vc >= 61) {
                    int p0 = (vmq + k * 4) >> 1;
                    if (vc == 61) {
                        pC[p0].x = v.x * v.x; pC[p0].y = v.y * v.y;
                        pC[p0 + 1].x = v.z * v.z; pC[p0 + 1].y = v.w * v.w;
                    } else if (vc == 62) {
                        pC[p0].z = v.x * v.x; pC[p0].w = v.y * v.y;
                        pC[p0 + 1].z = v.z * v.z; pC[p0 + 1].w = v.w * v.w;
                    } else {
                        pD[p0].x = v.x * v.x; pD[p0].y = v.y * v.y;
                        pD[p0 + 1].x = v.z * v.z; pD[p0 + 1].y = v.w * v.w;
                    }
                }
            }
            if (t < 192) {
                int d = t >> 6, m = t & 63;
                float v = nb[(size_t)d * HW + mb0 + m];
                if (d == 0)      ((float*)&pA[m >> 1])[m & 1] = v;
                else if (d == 1) ((float*)&pA[m >> 1])[2 + (m & 1)] = v;
                else             ((float*)&pB[m >> 1])[m & 1] = v;
            } else {
                int m = t - 192;
                ((float*)&pB[m >> 1])[2 + (m & 1)] = mb[mb0 + m];
            }
        }
        __syncthreads();

        // ---- w generation (packed f32x2) -> fp16 P tile ----
        {
            char* prow = P_sh + q * PSTR;
            #pragma unroll 4
            for (int k = 0; k < 16; k++) {
                const int p = mh * 16 + k;
                const ulonglong2 uab = *(const ulonglong2*)(&pA[p]);
                const ulonglong2 ucd = *(const ulonglong2*)(&pB[p]);
                unsigned long long c2, a2, w2;
                MUL2(c2, uab.x, qxx);
                FMA2(c2, uab.y, qyy, c2);
                FMA2(c2, ucd.x, qzz, c2);
                FMA2(a2, c2, kk2, bb2);
                float a0, a1;
                upk2(a2, a0, a1);
                w2 = pk2(ex2f(a0), ex2f(a1));
                MUL2(w2, w2, ucd.y);                       // * mask
                ADD2(a_sumw, a_sumw, w2);
                FMA2(a_swc, w2, c2, a_swc);
                const ulonglong2 usq = *(const ulonglong2*)(&pC[p]);
                const unsigned long long u63 = *(const unsigned long long*)(&pD[p]);
                FMA2(a_s0, w2, usq.x, a_s0);
                FMA2(a_s1, w2, usq.y, a_s1);
                FMA2(a_s2, w2, u63, a_s2);
                float w0, w1;
                upk2(w2, w0, w1);
                *(uint32_t*)(prow + p * 4) = cvt_f16x2(w0, w1);
            }
        }
        __syncthreads();

        // ---- mma: 128q x 64ch x 64m ----
        #pragma unroll
        for (int kk = 0; kk < 4; kk++) {
            uint32_t a[2][4], bf[2][4];
            ldsm_x4(a[0][0], a[0][1], a[0][2], a[0][3], aAddr + kk * 32);
            ldsm_x4(a[1][0], a[1][1], a[1][2], a[1][3], aAddr + 16 * PSTR + kk * 32);
            ldsm_x4(bf[0][0], bf[0][1], bf[0][2], bf[0][3], bAddr + kk * 32);
            ldsm_x4(bf[1][0], bf[1][1], bf[1][2], bf[1][3], bAddr + 16 * PSTR + kk * 32);
            #pragma unroll
            for (int i = 0; i < 2; i++) {
                #pragma unroll
                for (int j = 0; j < 4; j++)
                    mma16816(acc[i][j], a[i], bf[j >> 1][j & 1], bf[j >> 1][(j & 1) + 2]);
            }
        }
    }

    // ---- extras reduction + write ----
    {
        float lo, hi, sumw, swc, s0, s1, s2;
        upk2(a_sumw, lo, hi); sumw = lo + hi;
        upk2(a_swc,  lo, hi); swc  = lo + hi;
        upk2(a_s0,   lo, hi); s0   = lo + hi;
        upk2(a_s1,   lo, hi); s1   = lo + hi;
        upk2(a_s2,   lo, hi); s2   = lo + hi;
        sumw += __shfl_xor_sync(0xffffffffu, sumw, 1);
        swc  += __shfl_xor_sync(0xffffffffu, swc, 1);
        s0   += __shfl_xor_sync(0xffffffffu, s0, 1);
        s1   += __shfl_xor_sync(0xffffffffu, s1, 1);
        s2   += __shfl_xor_sync(0xffffffffu, s2, 1);
        if (mh == 0) {
            int slot = slot0 + q;
            g_sumw[b][seg][slot] = sumw;
            g_swc [b][seg][slot] = swc;
            g_sq  [b][seg][slot][0] = s0;
            g_sq  [b][seg][slot][1] = s1;
            g_sq  [b][seg][slot][2] = s2;
        }
    }

    // ---- write mma partials ----
    {
        const int g = lid >> 2, tg = (lid & 3) * 2;
        #pragma unroll
        for (int i = 0; i < 2; i++) {
            #pragma unroll
            for (int j = 0; j < 4; j++) {
                int slot = slot0 + wq + 16 * i + g;
                int ch = wc + 8 * j + tg;
                *(float2*)&g_acc[b][seg][slot][ch]     = make_float2(acc[i][j][0], acc[i][j][1]);
                *(float2*)&g_acc[b][seg][slot + 8][ch] = make_float2(acc[i][j][2], acc[i][j][3]);
            }
        }
    }
}

// -------------------------------------------------------------------------
// Finalize: one block per (output pixel, batch). Invalid pixels -> zeros.
// Valid: sum segments (uniform exp offset cancels), normalize, write.
// -------------------------------------------------------------------------
__global__ void k_final(float* __restrict__ out, QParam qp)
{
    const int qidx = blockIdx.x;
    const int b    = blockIdx.y;
    const int t    = threadIdx.x;
    const int v = qidx >> 6, u = qidx & 63;

    if (!q_valid(u, v)) {
        out[((size_t)b * COUT + 5 + t) * NQ + qidx] = 0.f;
        if (t < 5) out[((size_t)b * COUT + t) * NQ + qidx] = 0.f;
        return;
    }
    const int slot = qp.rowstart[v] + (u - qp.umin[v]);

    __shared__ float sD, s_swc, s_sq[3], s_mean[3];

    if (t == 0) {
        float sumw = 0.f, swc = 0.f, q0 = 0.f, q1 = 0.f, q2 = 0.f;
        for (int i = 0; i < NSEG; i++) {
            sumw += g_sumw[b][i][slot];
            swc  += g_swc [b][i][slot];
            q0   += g_sq  [b][i][slot][0];
            q1   += g_sq  [b][i][slot][1];
            q2   += g_sq  [b][i][slot][2];
        }
        sD = sumw + 1e-9f;
        s_swc = swc; s_sq[0] = q0; s_sq[1] = q1; s_sq[2] = q2;
    }
    __syncthreads();

    const float D = sD;
    float a = 0.f;
    for (int i = 0; i < NSEG; i++) a += g_acc[b][i][slot][t];
    float mapped = a / D;
    out[((size_t)b * COUT + 5 + t) * NQ + qidx] = mapped;
    if (t >= 61) s_mean[t - 61] = mapped;
    __syncthreads();

    if (t == 0) {
        float var = (s_sq[0] / D - s_mean[0] * s_mean[0])
                  + (s_sq[1] / D - s_mean[1] * s_mean[1])
                  + (s_sq[2] / D - s_mean[2] * s_mean[2]);
        float x, y, z;
        qn_of(qidx, x, y, z);
        out[((size_t)b * COUT + 0) * NQ + qidx] = s_swc / D;
        out[((size_t)b * COUT + 1) * NQ + qidx] = var;
        out[((size_t)b * COUT + 2) * NQ + qidx] = x;
        out[((size_t)b * COUT + 3) * NQ + qidx] = y;
        out[((size_t)b * COUT + 4) * NQ + qidx] = z;
    }
}

extern "C" void kernel_launch(void* const* d_in, const int* in_sizes, int n_in,
                              void* d_out, int out_size)
{
    const float* fea = (const float*)d_in[0];
    const float* nrm = (const float*)d_in[1];
    const float* msk = (const float*)d_in[2];
    const float* lqn = (const float*)d_in[3];
    float* out = (float*)d_out;

    // Host-side analytic valid-query table (deterministic, capture-safe).
    QParam qp;
    int n = 0;
    for (int v = 0; v < 64; v++) {
        qp.rowstart[v] = n;
        int first = -1;
        for (int u = 0; u < 64; u++) {
            int du = 2 * u - 63, dv = 2 * v - 63;
            if (du * du + dv * dv < 1024) {
                if (first < 0) first = u;
                n++;
            }
        }
        qp.umin[v] = (first < 0) ? 0 : first;
    }
    qp.rowstart[64] = n;
    qp.nv = n;

    const int qblocks = (n + QT - 1) / QT;   // 7

    dim3 g1(qblocks, NSEG, BS);
    k_main<<<g1, 256>>>(fea, nrm, msk, lqn, qp);
    k_final<<<dim3(NQ, BS), 64>>>(out, qp);
}